// round 15
// baseline (speedup 1.0000x reference)
#include <cuda_runtime.h>
#include <math.h>
#include <stdint.h>

// ---- problem constants ----
#define Bg   64
#define Nn   1024
#define Dd   128
#define EPG  8192
#define NTOT (Bg*Nn)      // 65536
#define ETOT (Bg*EPG)     // 524288
#define KP   820          // kept nodes per graph
#define BK   (Bg*KP)      // 52480
#define NEGS 0.2f
#define LAMBDA 1.0f
#define TJ   8            // columns per sparsemax tile
#define SHP  9            // shared pitch (bank-conflict free)
#define NQ   26           // ceil(KP/32)
#define CAP  64           // bucket capacity (pooled-edge columns)

// ---- device scratch ----
__device__ int    g_cnt_out[NTOT];
__device__ int    g_cnt_in[NTOT];
__device__ float  g_sn[NTOT];
__device__ float  g_dn[NTOT];
__device__ double g_agg[NTOT * Dd];   // segment-sum accumulator (double)
__device__ double g_wa_d[Dd];
__device__ float  g_score[NTOT];
__device__ int    g_mask[NTOT];
__device__ float  g_wsrc[BK];
__device__ float  g_wdst[BK];
__device__ int    g_pnode[BK];
__device__ int    g_cnt2[BK];
__device__ int    g2_row[BK * CAP];
__device__ float  g2_val[BK * CAP];

// XLA f32 tanh (Eigen rational approximation, as emitted by XLA's elemental IR)
__device__ __forceinline__ float tanh_xla(float x) {
    float ax = fabsf(x);
    float cx = fminf(fmaxf(x, -7.90531110763549805f), 7.90531110763549805f);
    float x2 = cx * cx;
    float p = fmaf(x2, -2.76076847742355e-16f, 2.00018790482477e-13f);
    p = fmaf(p, x2, -8.60467152213735e-11f);
    p = fmaf(p, x2, 5.12229709037114e-08f);
    p = fmaf(p, x2, 1.48572235717979e-05f);
    p = fmaf(p, x2, 6.37261928875436e-04f);
    p = fmaf(p, x2, 4.89352455891786e-03f);
    p = p * cx;
    float q = fmaf(x2, 1.19825839466702e-06f, 1.18534705686654e-04f);
    q = fmaf(q, x2, 2.26843463243900e-03f);
    q = fmaf(q, x2, 4.89352518554385e-03f);
    float r = p / q;
    return (ax < 0.0004f) ? x : r;
}

__global__ void __launch_bounds__(256) k_init() {
    int i = blockIdx.x * blockDim.x + threadIdx.x;
    if (i < NTOT) { g_cnt_out[i] = 0; g_cnt_in[i] = 0; g_mask[i] = -1; }
    if (i < BK)   { g_cnt2[i] = 0; }
}

// per-edge degree counts only (CSR no longer needed)
__global__ void __launch_bounds__(256) k_count(const int* __restrict__ src,
                                               const int* __restrict__ dst) {
    int e = blockIdx.x * blockDim.x + threadIdx.x;
    if (e < ETOT) {
        atomicAdd(&g_cnt_out[src[e]], 1);
        atomicAdd(&g_cnt_in[dst[e]], 1);
    }
}

// fused: wa = W@a (blocks 0..15) + deg^-0.5 (blocks 16..271) + zero agg (rest)
__global__ void __launch_bounds__(256) k_prep(const float* __restrict__ W,
                                              const float* __restrict__ a) {
    if (blockIdx.x < 16) {
        int warp = (blockIdx.x * 256 + threadIdx.x) >> 5;
        int lane = threadIdx.x & 31;
        if (warp < Dd) {
            double s = 0.0;
            for (int k = lane; k < Dd; k += 32)
                s += (double)W[warp * Dd + k] * (double)a[k];
            #pragma unroll
            for (int o = 16; o; o >>= 1) s += __shfl_xor_sync(0xffffffffu, s, o);
            if (lane == 0) g_wa_d[warp] = s;
        }
    } else if (blockIdx.x < 272) {
        int i = (blockIdx.x - 16) * 256 + threadIdx.x;
        if (i < NTOT) {
            double od = (double)max(g_cnt_out[i], 1);
            double id = (double)max(g_cnt_in[i], 1);
            g_sn[i] = (float)(1.0 / sqrt(od));
            g_dn[i] = (float)(1.0 / sqrt(id));
        }
    } else {
        int i = (blockIdx.x - 272) * 256 + threadIdx.x;
        if (i < NTOT * Dd) g_agg[i] = 0.0;
    }
}

// edge-parallel segment-sum: one warp per edge, RED.F64 into g_agg[dst].
// elementwise term (double)((feat*sn)*v) identical to ref's f32 chain;
// double accumulation order is atomic-random (reassoc noise ~1e-16 rel).
__global__ void __launch_bounds__(256) k_edge(const int* __restrict__ src,
                                              const int* __restrict__ dst,
                                              const float* __restrict__ ef,
                                              const float* __restrict__ feat) {
    int e = (blockIdx.x * 256 + threadIdx.x) >> 5;
    int lane = threadIdx.x & 31;
    if (e >= ETOT) return;
    int s = src[e], d = dst[e];
    if (s == d) return;                       // nonself mask (adds exact 0 otherwise)
    float v = ef[e];
    if (v == 0.f) return;
    float sn = g_sn[s];
    float4 f = ((const float4*)(feat + (size_t)s * Dd))[lane];
    double* ag = g_agg + (size_t)d * Dd + lane * 4;
    atomicAdd(ag + 0, (double)((f.x * sn) * v));
    atomicAdd(ag + 1, (double)((f.y * sn) * v));
    atomicAdd(ag + 2, (double)((f.z * sn) * v));
    atomicAdd(ag + 3, (double)((f.w * sn) * v));
}

// dense scoring: warp per node; reads g_agg in exact XLA float2 lane layout;
// identical info tree + double dp + XLA sigmoid gate.
__global__ void __launch_bounds__(256) k_info(const float* __restrict__ feat,
                                              float* __restrict__ out_xs) {
    int gw = (blockIdx.x * blockDim.x + threadIdx.x) >> 5;
    int lane = threadIdx.x & 31;
    if (gw >= NTOT) return;
    int node = gw;
    float2 fva = ((const float2*)(feat + (size_t)node * Dd))[lane];        // 2L,2L+1
    float2 fvb = ((const float2*)(feat + (size_t)node * Dd + 64))[lane];   // 64+2L,65+2L
    const double* ag = g_agg + (size_t)node * Dd;
    double ga0 = ag[2 * lane];
    double ga1 = ag[2 * lane + 1];
    double gb0 = ag[64 + 2 * lane];
    double gb1 = ag[65 + 2 * lane];
    float dnf = g_dn[node];
    float g0 = (float)ga0, g1 = (float)ga1, g2v = (float)gb0, g3 = (float)gb1;
    float t0 = fabsf(fva.x - g0 * dnf);
    float t1 = fabsf(fva.y - g1 * dnf);
    float t2 = fabsf(fvb.x - g2v * dnf);
    float t3 = fabsf(fvb.y - g3 * dnf);
    float acc = ((t0 + t1) + t2) + t3;
    #pragma unroll
    for (int o = 16; o; o >>= 1)
        acc += __shfl_down_sync(0xffffffffu, acc, o);
    double dp_d = (double)fva.x * g_wa_d[2 * lane + 0]
                + (double)fva.y * g_wa_d[2 * lane + 1]
                + (double)fvb.x * g_wa_d[64 + 2 * lane + 0]
                + (double)fvb.y * g_wa_d[64 + 2 * lane + 1];
    #pragma unroll
    for (int o = 16; o; o >>= 1)
        dp_d += __shfl_xor_sync(0xffffffffu, dp_d, o);
    if (lane == 0) {
        float lr = (float)dp_d;
        float ll = (lr >= 0.f) ? lr : NEGS * lr;
        float t = tanh_xla(0.5f * ll);
        float attn = 0.5f * t + 0.5f;
        float sc = acc * attn;
        g_score[node] = sc;
        out_xs[node] = sc;
    }
}

// per-graph top-K via bitonic 1024 (desc by score, ties asc by index)
__global__ void __launch_bounds__(1024) k_topk(float* __restrict__ out_perm) {
    __shared__ float skey[Nn];
    __shared__ int   sidx[Nn];
    int b = blockIdx.x, tid = threadIdx.x;
    skey[tid] = g_score[b * Nn + tid];
    sidx[tid] = tid;
    __syncthreads();
    for (int k = 2; k <= Nn; k <<= 1) {
        for (int j = k >> 1; j > 0; j >>= 1) {
            int i = tid, ixj = i ^ j;
            if (ixj > i) {
                float ka = skey[i], kb = skey[ixj];
                int ia = sidx[i], ib = sidx[ixj];
                bool up = ((i & k) == 0);
                bool bBeforeA = (kb > ka) || (kb == ka && ib < ia);
                bool aBeforeB = (ka > kb) || (ka == kb && ia < ib);
                bool sw = up ? bBeforeA : aBeforeB;
                if (sw) { skey[i] = kb; skey[ixj] = ka; sidx[i] = ib; sidx[ixj] = ia; }
            }
            __syncthreads();
        }
    }
    if (tid < KP) {
        int node = b * Nn + sidx[tid];
        int p = b * KP + tid;
        g_pnode[p] = node;
        g_mask[node] = p;
        out_perm[p] = (float)node;
    }
}

// direct-bucket CSR of valid pooled edges, grouped by pooled column
__global__ void __launch_bounds__(256) k_scatter2(const int* __restrict__ src,
                                                  const int* __restrict__ dst,
                                                  const float* __restrict__ ef) {
    int e = blockIdx.x * blockDim.x + threadIdx.x;
    if (e < ETOT) {
        int nr = g_mask[src[e]], nc = g_mask[dst[e]];
        if (nr >= 0 && nc >= 0) {
            int slot = atomicAdd(&g_cnt2[nc], 1);
            if (slot < CAP) {
                g2_row[nc * CAP + slot] = nr % KP;
                g2_val[nc * CAP + slot] = LAMBDA * ef[e];
            }
        }
    }
}

__global__ void __launch_bounds__(256) k_pool(const float* __restrict__ feat,
                                              const float* __restrict__ att,
                                              float* __restrict__ out_fp) {
    int p = (blockIdx.x * blockDim.x + threadIdx.x) >> 5;
    int lane = threadIdx.x & 31;
    if (p >= BK) return;
    int node = g_pnode[p];
    float4 fv = ((const float4*)(feat + (size_t)node * Dd))[lane];
    ((float4*)(out_fp + (size_t)p * Dd))[lane] = fv;
    float4 a1 = ((const float4*)att)[lane];
    float4 a2 = ((const float4*)(att + Dd))[lane];
    double s1 = (double)fv.x * a1.x + (double)fv.y * a1.y
              + (double)fv.z * a1.z + (double)fv.w * a1.w;
    double s2 = (double)fv.x * a2.x + (double)fv.y * a2.y
              + (double)fv.z * a2.z + (double)fv.w * a2.w;
    for (int o = 16; o; o >>= 1) {
        s1 += __shfl_xor_sync(0xffffffffu, s1, o);
        s2 += __shfl_xor_sync(0xffffffffu, s2, o);
    }
    if (lane == 0) { g_wsrc[p] = (float)s1; g_wdst[p] = (float)s2; }
}

// fused Wblk build + edge adds + sparsemax (Michelot, f32, warm start) + transposed write
__global__ void __launch_bounds__(256) k_spm(float* __restrict__ out_w) {
    __shared__ float sh[KP * SHP];
    int b = blockIdx.y;
    int j0 = blockIdx.x * TJ;
    int ncols = KP - j0; if (ncols > TJ) ncols = TJ;
    int t = threadIdx.x;
    int w = t & (TJ - 1), iq = t >> 3;
    int wp = t >> 5, lane = t & 31;

    if (w < ncols) {
        float wdj = g_wdst[(size_t)b * KP + j0 + w];
        for (int i = iq; i < KP; i += 32) {
            float v = g_wsrc[b * KP + i] + wdj;
            sh[i * SHP + w] = (v >= 0.f) ? v : NEGS * v;
        }
    }
    __syncthreads();

    if (wp < ncols) {
        int c = b * KP + j0 + wp;
        int cnt = g_cnt2[c]; if (cnt > CAP) cnt = CAP;
        int base = c * CAP;
        for (int e = lane; e < cnt; e += 32)
            atomicAdd(&sh[g2_row[base + e] * SHP + wp], g2_val[base + e]);
    }
    __syncthreads();

    if (wp < ncols) {
        float z[NQ];
        #pragma unroll
        for (int q = 0; q < NQ; q++) {
            int i = q * 32 + lane;
            z[q] = (i < KP) ? sh[i * SHP + wp] : -1e30f;
        }
        float s = 0.f, zmax = -1e30f;
        #pragma unroll
        for (int q = 0; q < NQ; q++) {
            int i = q * 32 + lane;
            if (i < KP) s += z[q];
            zmax = fmaxf(zmax, z[q]);
        }
        #pragma unroll
        for (int o = 16; o; o >>= 1) {
            s += __shfl_xor_sync(0xffffffffu, s, o);
            zmax = fmaxf(zmax, __shfl_xor_sync(0xffffffffu, zmax, o));
        }
        float tau = fmaxf((s - 1.f) / (float)KP, zmax - 1.f);
        int kprev = 0x7fffffff;
        for (int it = 0; it < 60; it++) {
            float s2 = 0.f; int k2 = 0;
            #pragma unroll
            for (int q = 0; q < NQ; q++) {
                float zz = z[q];
                if (zz > tau) { s2 += zz; k2++; }
            }
            #pragma unroll
            for (int o = 16; o; o >>= 1) {
                s2 += __shfl_xor_sync(0xffffffffu, s2, o);
                k2 += __shfl_xor_sync(0xffffffffu, k2, o);
            }
            if (k2 >= kprev || k2 == 0) break;
            float ntau = (s2 - 1.f) / (float)k2;
            if (ntau == tau) break;
            tau = ntau;
            kprev = k2;
        }
        #pragma unroll
        for (int q = 0; q < NQ; q++) {
            int i = q * 32 + lane;
            if (i < KP) {
                float d = z[q] - tau;
                sh[i * SHP + wp] = (d > 1e-9f) ? d : 0.f;
            }
        }
    }
    __syncthreads();

    {
        size_t base = (size_t)b * KP * KP;
        int j = j0 + w;
        if (j < KP && w < ncols) {
            for (int i = iq; i < KP; i += 32)
                out_w[base + (size_t)i * KP + j] = sh[i * SHP + w];
        }
    }
}

extern "C" void kernel_launch(void* const* d_in, const int* in_sizes, int n_in,
                              void* d_out, int out_size) {
    const float* feat = (const float*)d_in[0];
    const float* ef   = (const float*)d_in[1];
    const float* W    = (const float*)d_in[2];
    const float* a    = (const float*)d_in[3];
    const float* att  = (const float*)d_in[4];
    const int*   src  = (const int*)d_in[5];
    const int*   dst  = (const int*)d_in[6];

    float* out      = (float*)d_out;
    float* out_fp   = out;                               // [BK, D]
    float* out_w    = out + (size_t)BK * Dd;             // [B, KP, KP]
    float* out_perm = out_w + (size_t)BK * KP;           // [BK]
    float* out_xs   = out_perm + BK;                     // [NTOT]

    k_init<<<(NTOT + 255) / 256, 256>>>();                          // 1
    k_count<<<(ETOT + 255) / 256, 256>>>(src, dst);                 // 2
    k_prep<<<272 + (NTOT * Dd + 255) / 256, 256>>>(W, a);           // 3
    k_edge<<<(ETOT * 32 + 255) / 256, 256>>>(src, dst, ef, feat);   // 4 <- ncu slot
    k_info<<<(NTOT * 32 + 255) / 256, 256>>>(feat, out_xs);         // 5
    k_topk<<<Bg, 1024>>>(out_perm);
    k_scatter2<<<(ETOT + 255) / 256, 256>>>(src, dst, ef);
    k_pool<<<(BK * 32 + 255) / 256, 256>>>(feat, att, out_fp);

    dim3 g((KP + TJ - 1) / TJ, Bg);
    k_spm<<<g, 256>>>(out_w);
}